// round 3
// baseline (speedup 1.0000x reference)
#include <cuda_runtime.h>

#define N_NODES 50000
#define N_EDGES 800000
#define NEG_SLOPE 0.2f

// ---------------- scratch (device globals) ---------------------------------
__device__ __align__(16) float g_xh[(size_t)N_NODES * 128]; // x @ W
__device__ __align__(16) float g_si[N_NODES * 4];           // <xh, a_i> per head
__device__ __align__(16) float g_sj[N_NODES * 4];           // <xh, a_j> per head
__device__ int   g_m[N_NODES * 4];                          // segment max (ordered-int keys)
__device__ float g_sew[32];                                 // folded We * a_e  [c][h]
__device__ int   g_cur[N_NODES];                            // counts -> cursors
__device__ int   g_off[N_NODES + 1];                        // CSR offsets by dst
__device__ int   g_ssrc[N_EDGES];                           // dst-sorted src ids
__device__ __align__(16) float g_salpha[(size_t)N_EDGES * 4]; // dst-sorted logits

// order-preserving float->int key
__device__ __forceinline__ int f2key(float v) {
    int i = __float_as_int(v);
    return (i >= 0) ? i : (i ^ 0x7fffffff);
}

// ---------------- K0: init m sentinel, counts, fold We*a_e -----------------
__global__ void k_init(const float* __restrict__ We, const float* __restrict__ att) {
    int i = blockIdx.x * blockDim.x + threadIdx.x;
    if (i < N_NODES * 4) g_m[i] = 0x80000000;
    if (i < N_NODES) g_cur[i] = 0;
    if (i == 0) g_off[N_NODES] = N_EDGES;
    if (i < 32) {
        int h = i & 3, c = i >> 2;
        float s = 0.0f;
        #pragma unroll
        for (int p = 0; p < 4; p++)
            s += __ldg(We + c * 16 + h * 4 + p) * __ldg(att + h * 68 + 64 + p);
        g_sew[c * 4 + h] = s;
    }
}

// ---------------- K1: histogram of dst --------------------------------------
__global__ void k_hist(const int* __restrict__ ei) {
    int e = blockIdx.x * blockDim.x + threadIdx.x;
    if (e < N_EDGES) atomicAdd(&g_cur[__ldg(ei + N_EDGES + e)], 1);
}

// ---------------- K2: exclusive scan (single block, 1024 threads) ----------
__global__ __launch_bounds__(1024) void k_scan() {
    __shared__ int part[1024];
    const int PER = (N_NODES + 1023) / 1024;  // 49
    int t = threadIdx.x;
    int base = t * PER;
    int s = 0;
    for (int i = 0; i < PER; i++) {
        int idx = base + i;
        if (idx < N_NODES) s += g_cur[idx];
    }
    part[t] = s;
    __syncthreads();
    // Hillis-Steele inclusive scan
    for (int off = 1; off < 1024; off <<= 1) {
        int v = (t >= off) ? part[t - off] : 0;
        __syncthreads();
        part[t] += v;
        __syncthreads();
    }
    int run = part[t] - s;  // exclusive prefix of this chunk
    for (int i = 0; i < PER; i++) {
        int idx = base + i;
        if (idx < N_NODES) {
            int c = g_cur[idx];
            g_off[idx] = run;
            g_cur[idx] = run;  // cursor for scatter
            run += c;
        }
    }
}

// ---------------- K3: xh = x @ W (+ s_i, s_j in epilogue) ------------------
__global__ __launch_bounds__(256) void k_gemm(const float* __restrict__ x,
                                              const float* __restrict__ W,
                                              const float* __restrict__ att) {
    __shared__ __align__(16) float sW[64 * 128];
    int t = threadIdx.x;
    int row = t & 63;
    int cg  = t >> 6;                      // head index 0..3
    int grow = blockIdx.x * 64 + row;
    int xrow = grow < N_NODES ? grow : N_NODES - 1;

    float acc[32];
    #pragma unroll
    for (int i = 0; i < 32; i++) acc[i] = 0.0f;

    const float4* xp = (const float4*)(x + (size_t)xrow * 128);

    #pragma unroll
    for (int phase = 0; phase < 2; phase++) {
        __syncthreads();
        const float4* wsrc = (const float4*)(W + phase * 64 * 128);
        float4* wdst = (float4*)sW;
        #pragma unroll
        for (int i = 0; i < 8; i++) wdst[t + i * 256] = __ldg(wsrc + t + i * 256);
        __syncthreads();

        #pragma unroll
        for (int k4 = 0; k4 < 16; k4++) {
            float4 xv = __ldg(xp + phase * 16 + k4);
            #pragma unroll
            for (int kk = 0; kk < 4; kk++) {
                float xs = (kk == 0) ? xv.x : (kk == 1) ? xv.y : (kk == 2) ? xv.z : xv.w;
                const float4* wrow = (const float4*)(sW + (k4 * 4 + kk) * 128 + cg * 32);
                #pragma unroll
                for (int j = 0; j < 8; j++) {
                    float4 w = wrow[j];
                    acc[j * 4 + 0] += xs * w.x;
                    acc[j * 4 + 1] += xs * w.y;
                    acc[j * 4 + 2] += xs * w.z;
                    acc[j * 4 + 3] += xs * w.w;
                }
            }
        }
    }

    if (grow < N_NODES) {
        float4* op = (float4*)(g_xh + (size_t)grow * 128 + cg * 32);
        float si = 0.0f, sj = 0.0f;
        const float* ap = att + cg * 68;
        #pragma unroll
        for (int j = 0; j < 8; j++) {
            op[j] = make_float4(acc[j*4+0], acc[j*4+1], acc[j*4+2], acc[j*4+3]);
            #pragma unroll
            for (int cc = 0; cc < 4; cc++) {
                int o = j * 4 + cc;
                si += acc[o] * __ldg(ap + o);
                sj += acc[o] * __ldg(ap + 32 + o);
            }
        }
        g_si[grow * 4 + cg] = si;
        g_sj[grow * 4 + cg] = sj;
    }
}

// ---------------- K4: edge logits + segment max + scatter into CSR ---------
__global__ void k_edge(const int* __restrict__ ei, const float* __restrict__ eattr) {
    int e = blockIdx.x * blockDim.x + threadIdx.x;
    if (e >= N_EDGES) return;
    int src = __ldg(ei + e);
    int dst = __ldg(ei + N_EDGES + e);
    float4 f0 = __ldg((const float4*)eattr + (size_t)e * 2);
    float4 f1 = __ldg((const float4*)eattr + (size_t)e * 2 + 1);
    float f[8] = {f0.x, f0.y, f0.z, f0.w, f1.x, f1.y, f1.z, f1.w};
    float4 si = *(const float4*)(g_si + dst * 4);
    float4 sj = *(const float4*)(g_sj + src * 4);
    float sih[4] = {si.x, si.y, si.z, si.w};
    float sjh[4] = {sj.x, sj.y, sj.z, sj.w};
    float a[4];
    #pragma unroll
    for (int h = 0; h < 4; h++) {
        float se = 0.0f;
        #pragma unroll
        for (int c = 0; c < 8; c++) se += f[c] * g_sew[c * 4 + h];
        float v = sih[h] + sjh[h] + se;
        v = v > 0.0f ? v : NEG_SLOPE * v;
        a[h] = v;
        atomicMax(&g_m[dst * 4 + h], f2key(v));
    }
    int pos = atomicAdd(&g_cur[dst], 1);
    g_ssrc[pos] = src;
    *((float4*)g_salpha + pos) = make_float4(a[0], a[1], a[2], a[3]);
}

// ---------------- K5: warp-per-node aggregation (fused softmax) -------------
__global__ __launch_bounds__(256) void k_aggr(const float* __restrict__ bias,
                                              float* __restrict__ out) {
    int w = (blockIdx.x * blockDim.x + threadIdx.x) >> 5;
    if (w >= N_NODES) return;
    int lane = threadIdx.x & 31;
    int h = lane >> 3;

    int start = g_off[w];
    int end   = g_off[w + 1];

    int mk = g_m[w * 4 + h];
    float m = 0.0f;
    if (mk != (int)0x80000000)
        m = __int_as_float(mk >= 0 ? mk : (mk ^ 0x7fffffff));

    float ax = 0.0f, ay = 0.0f, az = 0.0f, aw = 0.0f, den = 0.0f;

    #pragma unroll 2
    for (int e = start; e < end; e++) {
        int src = __ldg(&g_ssrc[e]);
        float a = __ldg(&g_salpha[(size_t)e * 4 + h]);
        float ea = __expf(a - m);
        den += ea;
        float4 xv = __ldg((const float4*)(g_xh + (size_t)src * 128) + lane);
        ax += ea * xv.x; ay += ea * xv.y; az += ea * xv.z; aw += ea * xv.w;
    }

    float inv = 1.0f / (den + 1e-16f);
    float4 b = __ldg((const float4*)bias + lane);
    ((float4*)out)[(size_t)w * 32 + lane] =
        make_float4(ax * inv + b.x, ay * inv + b.y, az * inv + b.z, aw * inv + b.w);
}

// ---------------- launch ----------------------------------------------------
extern "C" void kernel_launch(void* const* d_in, const int* in_sizes, int n_in,
                              void* d_out, int out_size) {
    const float* x     = (const float*)d_in[0];
    const int*   ei    = (const int*)  d_in[1];
    const float* eattr = (const float*)d_in[2];
    const float* W     = (const float*)d_in[3];
    const float* We    = (const float*)d_in[4];
    const float* att   = (const float*)d_in[5];
    const float* bias  = (const float*)d_in[6];
    float* out = (float*)d_out;

    k_init <<<(N_NODES * 4 + 255) / 256, 256>>>(We, att);
    k_hist <<<(N_EDGES + 255) / 256, 256>>>(ei);
    k_scan <<<1, 1024>>>();
    k_gemm <<<(N_NODES + 63) / 64, 256>>>(x, W, att);
    k_edge <<<(N_EDGES + 255) / 256, 256>>>(ei, eattr);
    k_aggr <<<((size_t)N_NODES * 32 + 255) / 256, 256>>>(bias, out);
}

// round 4
// speedup vs baseline: 1.0020x; 1.0020x over previous
#include <cuda_runtime.h>

#define N_NODES 50000
#define N_EDGES 800000
#define NEG_SLOPE 0.2f

// ---------------- scratch (device globals) ---------------------------------
__device__ __align__(16) float g_xh[(size_t)N_NODES * 128]; // x @ W
__device__ __align__(16) float g_si[N_NODES * 4];           // <xh, a_i> per head
__device__ __align__(16) float g_sj[N_NODES * 4];           // <xh, a_j> per head
__device__ int   g_m[N_NODES * 4];                          // segment max (ordered-int keys)
__device__ float g_sew[32];                                 // folded We * a_e  [c][h]
__device__ int   g_cur[N_NODES];                            // counts -> cursors
__device__ int   g_off[N_NODES + 1];                        // CSR offsets by dst
__device__ int   g_ssrc[N_EDGES];                           // dst-sorted src ids
__device__ __align__(16) float g_salpha[(size_t)N_EDGES * 4]; // dst-sorted logits

// order-preserving float->int key
__device__ __forceinline__ int f2key(float v) {
    int i = __float_as_int(v);
    return (i >= 0) ? i : (i ^ 0x7fffffff);
}

// ---------------- K0: init m sentinel, counts, fold We*a_e -----------------
__global__ void k_init(const float* __restrict__ We, const float* __restrict__ att) {
    int i = blockIdx.x * blockDim.x + threadIdx.x;
    if (i < N_NODES * 4) g_m[i] = 0x80000000;
    if (i < N_NODES) g_cur[i] = 0;
    if (i == 0) g_off[N_NODES] = N_EDGES;
    if (i < 32) {
        int h = i & 3, c = i >> 2;
        float s = 0.0f;
        #pragma unroll
        for (int p = 0; p < 4; p++)
            s += __ldg(We + c * 16 + h * 4 + p) * __ldg(att + h * 68 + 64 + p);
        g_sew[c * 4 + h] = s;
    }
}

// ---------------- K1: histogram of dst --------------------------------------
__global__ void k_hist(const int* __restrict__ ei) {
    int e = blockIdx.x * blockDim.x + threadIdx.x;
    if (e < N_EDGES) atomicAdd(&g_cur[__ldg(ei + N_EDGES + e)], 1);
}

// ---------------- K2: exclusive scan (single block, 1024 threads) ----------
__global__ __launch_bounds__(1024) void k_scan() {
    __shared__ int part[1024];
    const int PER = (N_NODES + 1023) / 1024;  // 49
    int t = threadIdx.x;
    int base = t * PER;
    int s = 0;
    for (int i = 0; i < PER; i++) {
        int idx = base + i;
        if (idx < N_NODES) s += g_cur[idx];
    }
    part[t] = s;
    __syncthreads();
    // Hillis-Steele inclusive scan
    for (int off = 1; off < 1024; off <<= 1) {
        int v = (t >= off) ? part[t - off] : 0;
        __syncthreads();
        part[t] += v;
        __syncthreads();
    }
    int run = part[t] - s;  // exclusive prefix of this chunk
    for (int i = 0; i < PER; i++) {
        int idx = base + i;
        if (idx < N_NODES) {
            int c = g_cur[idx];
            g_off[idx] = run;
            g_cur[idx] = run;  // cursor for scatter
            run += c;
        }
    }
}

// ---------------- K3: xh = x @ W (+ s_i, s_j in epilogue) ------------------
__global__ __launch_bounds__(256) void k_gemm(const float* __restrict__ x,
                                              const float* __restrict__ W,
                                              const float* __restrict__ att) {
    __shared__ __align__(16) float sW[64 * 128];
    int t = threadIdx.x;
    int row = t & 63;
    int cg  = t >> 6;                      // head index 0..3
    int grow = blockIdx.x * 64 + row;
    int xrow = grow < N_NODES ? grow : N_NODES - 1;

    float acc[32];
    #pragma unroll
    for (int i = 0; i < 32; i++) acc[i] = 0.0f;

    const float4* xp = (const float4*)(x + (size_t)xrow * 128);

    #pragma unroll
    for (int phase = 0; phase < 2; phase++) {
        __syncthreads();
        const float4* wsrc = (const float4*)(W + phase * 64 * 128);
        float4* wdst = (float4*)sW;
        #pragma unroll
        for (int i = 0; i < 8; i++) wdst[t + i * 256] = __ldg(wsrc + t + i * 256);
        __syncthreads();

        #pragma unroll
        for (int k4 = 0; k4 < 16; k4++) {
            float4 xv = __ldg(xp + phase * 16 + k4);
            #pragma unroll
            for (int kk = 0; kk < 4; kk++) {
                float xs = (kk == 0) ? xv.x : (kk == 1) ? xv.y : (kk == 2) ? xv.z : xv.w;
                const float4* wrow = (const float4*)(sW + (k4 * 4 + kk) * 128 + cg * 32);
                #pragma unroll
                for (int j = 0; j < 8; j++) {
                    float4 w = wrow[j];
                    acc[j * 4 + 0] += xs * w.x;
                    acc[j * 4 + 1] += xs * w.y;
                    acc[j * 4 + 2] += xs * w.z;
                    acc[j * 4 + 3] += xs * w.w;
                }
            }
        }
    }

    if (grow < N_NODES) {
        float4* op = (float4*)(g_xh + (size_t)grow * 128 + cg * 32);
        float si = 0.0f, sj = 0.0f;
        const float* ap = att + cg * 68;
        #pragma unroll
        for (int j = 0; j < 8; j++) {
            op[j] = make_float4(acc[j*4+0], acc[j*4+1], acc[j*4+2], acc[j*4+3]);
            #pragma unroll
            for (int cc = 0; cc < 4; cc++) {
                int o = j * 4 + cc;
                si += acc[o] * __ldg(ap + o);
                sj += acc[o] * __ldg(ap + 32 + o);
            }
        }
        g_si[grow * 4 + cg] = si;
        g_sj[grow * 4 + cg] = sj;
    }
}

// ---------------- K4: edge logits + segment max + scatter into CSR ---------
__global__ void k_edge(const int* __restrict__ ei, const float* __restrict__ eattr) {
    int e = blockIdx.x * blockDim.x + threadIdx.x;
    if (e >= N_EDGES) return;
    int src = __ldg(ei + e);
    int dst = __ldg(ei + N_EDGES + e);
    float4 f0 = __ldg((const float4*)eattr + (size_t)e * 2);
    float4 f1 = __ldg((const float4*)eattr + (size_t)e * 2 + 1);
    float f[8] = {f0.x, f0.y, f0.z, f0.w, f1.x, f1.y, f1.z, f1.w};
    float4 si = *(const float4*)(g_si + dst * 4);
    float4 sj = *(const float4*)(g_sj + src * 4);
    float sih[4] = {si.x, si.y, si.z, si.w};
    float sjh[4] = {sj.x, sj.y, sj.z, sj.w};
    float a[4];
    #pragma unroll
    for (int h = 0; h < 4; h++) {
        float se = 0.0f;
        #pragma unroll
        for (int c = 0; c < 8; c++) se += f[c] * g_sew[c * 4 + h];
        float v = sih[h] + sjh[h] + se;
        v = v > 0.0f ? v : NEG_SLOPE * v;
        a[h] = v;
        atomicMax(&g_m[dst * 4 + h], f2key(v));
    }
    int pos = atomicAdd(&g_cur[dst], 1);
    g_ssrc[pos] = src;
    *((float4*)g_salpha + pos) = make_float4(a[0], a[1], a[2], a[3]);
}

// ---------------- K5: warp-per-node aggregation (fused softmax) -------------
__global__ __launch_bounds__(256) void k_aggr(const float* __restrict__ bias,
                                              float* __restrict__ out) {
    int w = (blockIdx.x * blockDim.x + threadIdx.x) >> 5;
    if (w >= N_NODES) return;
    int lane = threadIdx.x & 31;
    int h = lane >> 3;

    int start = g_off[w];
    int end   = g_off[w + 1];

    int mk = g_m[w * 4 + h];
    float m = 0.0f;
    if (mk != (int)0x80000000)
        m = __int_as_float(mk >= 0 ? mk : (mk ^ 0x7fffffff));

    float ax = 0.0f, ay = 0.0f, az = 0.0f, aw = 0.0f, den = 0.0f;

    #pragma unroll 2
    for (int e = start; e < end; e++) {
        int src = __ldg(&g_ssrc[e]);
        float a = __ldg(&g_salpha[(size_t)e * 4 + h]);
        float ea = __expf(a - m);
        den += ea;
        float4 xv = __ldg((const float4*)(g_xh + (size_t)src * 128) + lane);
        ax += ea * xv.x; ay += ea * xv.y; az += ea * xv.z; aw += ea * xv.w;
    }

    float inv = 1.0f / (den + 1e-16f);
    float4 b = __ldg((const float4*)bias + lane);
    ((float4*)out)[(size_t)w * 32 + lane] =
        make_float4(ax * inv + b.x, ay * inv + b.y, az * inv + b.z, aw * inv + b.w);
}

// ---------------- launch ----------------------------------------------------
extern "C" void kernel_launch(void* const* d_in, const int* in_sizes, int n_in,
                              void* d_out, int out_size) {
    const float* x     = (const float*)d_in[0];
    const int*   ei    = (const int*)  d_in[1];
    const float* eattr = (const float*)d_in[2];
    const float* W     = (const float*)d_in[3];
    const float* We    = (const float*)d_in[4];
    const float* att   = (const float*)d_in[5];
    const float* bias  = (const float*)d_in[6];
    float* out = (float*)d_out;

    k_init <<<(N_NODES * 4 + 255) / 256, 256>>>(We, att);
    k_hist <<<(N_EDGES + 255) / 256, 256>>>(ei);
    k_scan <<<1, 1024>>>();
    k_gemm <<<(N_NODES + 63) / 64, 256>>>(x, W, att);
    k_edge <<<(N_EDGES + 255) / 256, 256>>>(ei, eattr);
    k_aggr <<<((size_t)N_NODES * 32 + 255) / 256, 256>>>(bias, out);
}

// round 5
// speedup vs baseline: 1.0079x; 1.0059x over previous
#include <cuda_runtime.h>

#define N_NODES 50000
#define N_EDGES 800000
#define NEG_SLOPE 0.2f

// ---------------- scratch (device globals) ---------------------------------
__device__ __align__(16) float g_xh[(size_t)N_NODES * 128]; // x @ W
__device__ __align__(16) float g_si[N_NODES * 4];           // <xh, a_i> per head
__device__ __align__(16) float g_sj[N_NODES * 4];           // <xh, a_j> per head
__device__ int   g_m[N_NODES * 4];                          // segment max (ordered-int keys)
__device__ float g_sew[32];                                 // folded We * a_e  [c][h]
__device__ int   g_cur[N_NODES];                            // counts -> cursors
__device__ int   g_off[N_NODES + 1];                        // CSR offsets by dst
__device__ int   g_ssrc[N_EDGES];                           // dst-sorted src ids
__device__ __align__(16) float g_salpha[(size_t)N_EDGES * 4]; // dst-sorted logits

// order-preserving float->int key
__device__ __forceinline__ int f2key(float v) {
    int i = __float_as_int(v);
    return (i >= 0) ? i : (i ^ 0x7fffffff);
}

// ---------------- K0: init m sentinel, counts, fold We*a_e -----------------
__global__ void k_init(const float* __restrict__ We, const float* __restrict__ att) {
    int i = blockIdx.x * blockDim.x + threadIdx.x;
    if (i < N_NODES * 4) g_m[i] = 0x80000000;
    if (i < N_NODES) g_cur[i] = 0;
    if (i == 0) g_off[N_NODES] = N_EDGES;
    if (i < 32) {
        int h = i & 3, c = i >> 2;
        float s = 0.0f;
        #pragma unroll
        for (int p = 0; p < 4; p++)
            s += __ldg(We + c * 16 + h * 4 + p) * __ldg(att + h * 68 + 64 + p);
        g_sew[c * 4 + h] = s;
    }
}

// ---------------- K1: histogram of dst --------------------------------------
__global__ void k_hist(const int* __restrict__ ei) {
    int e = blockIdx.x * blockDim.x + threadIdx.x;
    if (e < N_EDGES) atomicAdd(&g_cur[__ldg(ei + N_EDGES + e)], 1);
}

// ---------------- K2: exclusive scan (single block, 1024 threads) ----------
__global__ __launch_bounds__(1024) void k_scan() {
    __shared__ int part[1024];
    const int PER = (N_NODES + 1023) / 1024;  // 49
    int t = threadIdx.x;
    int base = t * PER;
    int s = 0;
    for (int i = 0; i < PER; i++) {
        int idx = base + i;
        if (idx < N_NODES) s += g_cur[idx];
    }
    part[t] = s;
    __syncthreads();
    // Hillis-Steele inclusive scan
    for (int off = 1; off < 1024; off <<= 1) {
        int v = (t >= off) ? part[t - off] : 0;
        __syncthreads();
        part[t] += v;
        __syncthreads();
    }
    int run = part[t] - s;  // exclusive prefix of this chunk
    for (int i = 0; i < PER; i++) {
        int idx = base + i;
        if (idx < N_NODES) {
            int c = g_cur[idx];
            g_off[idx] = run;
            g_cur[idx] = run;  // cursor for scatter
            run += c;
        }
    }
}

// ---------------- K3: xh = x @ W (+ s_i, s_j in epilogue) ------------------
__global__ __launch_bounds__(256) void k_gemm(const float* __restrict__ x,
                                              const float* __restrict__ W,
                                              const float* __restrict__ att) {
    __shared__ __align__(16) float sW[64 * 128];
    int t = threadIdx.x;
    int row = t & 63;
    int cg  = t >> 6;                      // head index 0..3
    int grow = blockIdx.x * 64 + row;
    int xrow = grow < N_NODES ? grow : N_NODES - 1;

    float acc[32];
    #pragma unroll
    for (int i = 0; i < 32; i++) acc[i] = 0.0f;

    const float4* xp = (const float4*)(x + (size_t)xrow * 128);

    #pragma unroll
    for (int phase = 0; phase < 2; phase++) {
        __syncthreads();
        const float4* wsrc = (const float4*)(W + phase * 64 * 128);
        float4* wdst = (float4*)sW;
        #pragma unroll
        for (int i = 0; i < 8; i++) wdst[t + i * 256] = __ldg(wsrc + t + i * 256);
        __syncthreads();

        #pragma unroll
        for (int k4 = 0; k4 < 16; k4++) {
            float4 xv = __ldg(xp + phase * 16 + k4);
            #pragma unroll
            for (int kk = 0; kk < 4; kk++) {
                float xs = (kk == 0) ? xv.x : (kk == 1) ? xv.y : (kk == 2) ? xv.z : xv.w;
                const float4* wrow = (const float4*)(sW + (k4 * 4 + kk) * 128 + cg * 32);
                #pragma unroll
                for (int j = 0; j < 8; j++) {
                    float4 w = wrow[j];
                    acc[j * 4 + 0] += xs * w.x;
                    acc[j * 4 + 1] += xs * w.y;
                    acc[j * 4 + 2] += xs * w.z;
                    acc[j * 4 + 3] += xs * w.w;
                }
            }
        }
    }

    if (grow < N_NODES) {
        float4* op = (float4*)(g_xh + (size_t)grow * 128 + cg * 32);
        float si = 0.0f, sj = 0.0f;
        const float* ap = att + cg * 68;
        #pragma unroll
        for (int j = 0; j < 8; j++) {
            op[j] = make_float4(acc[j*4+0], acc[j*4+1], acc[j*4+2], acc[j*4+3]);
            #pragma unroll
            for (int cc = 0; cc < 4; cc++) {
                int o = j * 4 + cc;
                si += acc[o] * __ldg(ap + o);
                sj += acc[o] * __ldg(ap + 32 + o);
            }
        }
        g_si[grow * 4 + cg] = si;
        g_sj[grow * 4 + cg] = sj;
    }
}

// ---------------- K4: edge logits + segment max + scatter into CSR ---------
__global__ void k_edge(const int* __restrict__ ei, const float* __restrict__ eattr) {
    int e = blockIdx.x * blockDim.x + threadIdx.x;
    if (e >= N_EDGES) return;
    int src = __ldg(ei + e);
    int dst = __ldg(ei + N_EDGES + e);
    float4 f0 = __ldg((const float4*)eattr + (size_t)e * 2);
    float4 f1 = __ldg((const float4*)eattr + (size_t)e * 2 + 1);
    float f[8] = {f0.x, f0.y, f0.z, f0.w, f1.x, f1.y, f1.z, f1.w};
    float4 si = *(const float4*)(g_si + dst * 4);
    float4 sj = *(const float4*)(g_sj + src * 4);
    float sih[4] = {si.x, si.y, si.z, si.w};
    float sjh[4] = {sj.x, sj.y, sj.z, sj.w};
    float a[4];
    #pragma unroll
    for (int h = 0; h < 4; h++) {
        float se = 0.0f;
        #pragma unroll
        for (int c = 0; c < 8; c++) se += f[c] * g_sew[c * 4 + h];
        float v = sih[h] + sjh[h] + se;
        v = v > 0.0f ? v : NEG_SLOPE * v;
        a[h] = v;
        atomicMax(&g_m[dst * 4 + h], f2key(v));
    }
    int pos = atomicAdd(&g_cur[dst], 1);
    g_ssrc[pos] = src;
    *((float4*)g_salpha + pos) = make_float4(a[0], a[1], a[2], a[3]);
}

// ---------------- K5: warp-per-node aggregation (fused softmax) -------------
__global__ __launch_bounds__(256) void k_aggr(const float* __restrict__ bias,
                                              float* __restrict__ out) {
    int w = (blockIdx.x * blockDim.x + threadIdx.x) >> 5;
    if (w >= N_NODES) return;
    int lane = threadIdx.x & 31;
    int h = lane >> 3;

    int start = g_off[w];
    int end   = g_off[w + 1];

    int mk = g_m[w * 4 + h];
    float m = 0.0f;
    if (mk != (int)0x80000000)
        m = __int_as_float(mk >= 0 ? mk : (mk ^ 0x7fffffff));

    float ax = 0.0f, ay = 0.0f, az = 0.0f, aw = 0.0f, den = 0.0f;

    #pragma unroll 2
    for (int e = start; e < end; e++) {
        int src = __ldg(&g_ssrc[e]);
        float a = __ldg(&g_salpha[(size_t)e * 4 + h]);
        float ea = __expf(a - m);
        den += ea;
        float4 xv = __ldg((const float4*)(g_xh + (size_t)src * 128) + lane);
        ax += ea * xv.x; ay += ea * xv.y; az += ea * xv.z; aw += ea * xv.w;
    }

    float inv = 1.0f / (den + 1e-16f);
    float4 b = __ldg((const float4*)bias + lane);
    ((float4*)out)[(size_t)w * 32 + lane] =
        make_float4(ax * inv + b.x, ay * inv + b.y, az * inv + b.z, aw * inv + b.w);
}

// ---------------- launch ----------------------------------------------------
extern "C" void kernel_launch(void* const* d_in, const int* in_sizes, int n_in,
                              void* d_out, int out_size) {
    const float* x     = (const float*)d_in[0];
    const int*   ei    = (const int*)  d_in[1];
    const float* eattr = (const float*)d_in[2];
    const float* W     = (const float*)d_in[3];
    const float* We    = (const float*)d_in[4];
    const float* att   = (const float*)d_in[5];
    const float* bias  = (const float*)d_in[6];
    float* out = (float*)d_out;

    k_init <<<(N_NODES * 4 + 255) / 256, 256>>>(We, att);
    k_hist <<<(N_EDGES + 255) / 256, 256>>>(ei);
    k_scan <<<1, 1024>>>();
    k_gemm <<<(N_NODES + 63) / 64, 256>>>(x, W, att);
    k_edge <<<(N_EDGES + 255) / 256, 256>>>(ei, eattr);
    k_aggr <<<((size_t)N_NODES * 32 + 255) / 256, 256>>>(bias, out);
}

// round 6
// speedup vs baseline: 1.0092x; 1.0012x over previous
#include <cuda_runtime.h>

#define N_NODES 50000
#define N_EDGES 800000
#define NEG_SLOPE 0.2f

// ---------------- scratch (device globals) ---------------------------------
__device__ __align__(16) float g_xh[(size_t)N_NODES * 128]; // x @ W
__device__ __align__(16) float g_si[N_NODES * 4];           // <xh, a_i> per head
__device__ __align__(16) float g_sj[N_NODES * 4];           // <xh, a_j> per head
__device__ int   g_m[N_NODES * 4];                          // segment max (ordered-int keys)
__device__ float g_sew[32];                                 // folded We * a_e  [c][h]
__device__ int   g_cur[N_NODES];                            // counts -> cursors
__device__ int   g_off[N_NODES + 1];                        // CSR offsets by dst
__device__ int   g_ssrc[N_EDGES];                           // dst-sorted src ids
__device__ __align__(16) float g_salpha[(size_t)N_EDGES * 4]; // dst-sorted logits

// order-preserving float->int key
__device__ __forceinline__ int f2key(float v) {
    int i = __float_as_int(v);
    return (i >= 0) ? i : (i ^ 0x7fffffff);
}

// ---------------- K0: init m sentinel, counts, fold We*a_e -----------------
__global__ void k_init(const float* __restrict__ We, const float* __restrict__ att) {
    int i = blockIdx.x * blockDim.x + threadIdx.x;
    if (i < N_NODES * 4) g_m[i] = 0x80000000;
    if (i < N_NODES) g_cur[i] = 0;
    if (i == 0) g_off[N_NODES] = N_EDGES;
    if (i < 32) {
        int h = i & 3, c = i >> 2;
        float s = 0.0f;
        #pragma unroll
        for (int p = 0; p < 4; p++)
            s += __ldg(We + c * 16 + h * 4 + p) * __ldg(att + h * 68 + 64 + p);
        g_sew[c * 4 + h] = s;
    }
}

// ---------------- K1: histogram of dst --------------------------------------
__global__ void k_hist(const int* __restrict__ ei) {
    int e = blockIdx.x * blockDim.x + threadIdx.x;
    if (e < N_EDGES) atomicAdd(&g_cur[__ldg(ei + N_EDGES + e)], 1);
}

// ---------------- K2: exclusive scan (single block, 1024 threads) ----------
__global__ __launch_bounds__(1024) void k_scan() {
    __shared__ int part[1024];
    const int PER = (N_NODES + 1023) / 1024;  // 49
    int t = threadIdx.x;
    int base = t * PER;
    int s = 0;
    for (int i = 0; i < PER; i++) {
        int idx = base + i;
        if (idx < N_NODES) s += g_cur[idx];
    }
    part[t] = s;
    __syncthreads();
    // Hillis-Steele inclusive scan
    for (int off = 1; off < 1024; off <<= 1) {
        int v = (t >= off) ? part[t - off] : 0;
        __syncthreads();
        part[t] += v;
        __syncthreads();
    }
    int run = part[t] - s;  // exclusive prefix of this chunk
    for (int i = 0; i < PER; i++) {
        int idx = base + i;
        if (idx < N_NODES) {
            int c = g_cur[idx];
            g_off[idx] = run;
            g_cur[idx] = run;  // cursor for scatter
            run += c;
        }
    }
}

// ---------------- K3: xh = x @ W (+ s_i, s_j in epilogue) ------------------
__global__ __launch_bounds__(256) void k_gemm(const float* __restrict__ x,
                                              const float* __restrict__ W,
                                              const float* __restrict__ att) {
    __shared__ __align__(16) float sW[64 * 128];
    int t = threadIdx.x;
    int row = t & 63;
    int cg  = t >> 6;                      // head index 0..3
    int grow = blockIdx.x * 64 + row;
    int xrow = grow < N_NODES ? grow : N_NODES - 1;

    float acc[32];
    #pragma unroll
    for (int i = 0; i < 32; i++) acc[i] = 0.0f;

    const float4* xp = (const float4*)(x + (size_t)xrow * 128);

    #pragma unroll
    for (int phase = 0; phase < 2; phase++) {
        __syncthreads();
        const float4* wsrc = (const float4*)(W + phase * 64 * 128);
        float4* wdst = (float4*)sW;
        #pragma unroll
        for (int i = 0; i < 8; i++) wdst[t + i * 256] = __ldg(wsrc + t + i * 256);
        __syncthreads();

        #pragma unroll
        for (int k4 = 0; k4 < 16; k4++) {
            float4 xv = __ldg(xp + phase * 16 + k4);
            #pragma unroll
            for (int kk = 0; kk < 4; kk++) {
                float xs = (kk == 0) ? xv.x : (kk == 1) ? xv.y : (kk == 2) ? xv.z : xv.w;
                const float4* wrow = (const float4*)(sW + (k4 * 4 + kk) * 128 + cg * 32);
                #pragma unroll
                for (int j = 0; j < 8; j++) {
                    float4 w = wrow[j];
                    acc[j * 4 + 0] += xs * w.x;
                    acc[j * 4 + 1] += xs * w.y;
                    acc[j * 4 + 2] += xs * w.z;
                    acc[j * 4 + 3] += xs * w.w;
                }
            }
        }
    }

    if (grow < N_NODES) {
        float4* op = (float4*)(g_xh + (size_t)grow * 128 + cg * 32);
        float si = 0.0f, sj = 0.0f;
        const float* ap = att + cg * 68;
        #pragma unroll
        for (int j = 0; j < 8; j++) {
            op[j] = make_float4(acc[j*4+0], acc[j*4+1], acc[j*4+2], acc[j*4+3]);
            #pragma unroll
            for (int cc = 0; cc < 4; cc++) {
                int o = j * 4 + cc;
                si += acc[o] * __ldg(ap + o);
                sj += acc[o] * __ldg(ap + 32 + o);
            }
        }
        g_si[grow * 4 + cg] = si;
        g_sj[grow * 4 + cg] = sj;
    }
}

// ---------------- K4: edge logits + segment max + scatter into CSR ---------
__global__ void k_edge(const int* __restrict__ ei, const float* __restrict__ eattr) {
    int e = blockIdx.x * blockDim.x + threadIdx.x;
    if (e >= N_EDGES) return;
    int src = __ldg(ei + e);
    int dst = __ldg(ei + N_EDGES + e);
    float4 f0 = __ldg((const float4*)eattr + (size_t)e * 2);
    float4 f1 = __ldg((const float4*)eattr + (size_t)e * 2 + 1);
    float f[8] = {f0.x, f0.y, f0.z, f0.w, f1.x, f1.y, f1.z, f1.w};
    float4 si = *(const float4*)(g_si + dst * 4);
    float4 sj = *(const float4*)(g_sj + src * 4);
    float sih[4] = {si.x, si.y, si.z, si.w};
    float sjh[4] = {sj.x, sj.y, sj.z, sj.w};
    float a[4];
    #pragma unroll
    for (int h = 0; h < 4; h++) {
        float se = 0.0f;
        #pragma unroll
        for (int c = 0; c < 8; c++) se += f[c] * g_sew[c * 4 + h];
        float v = sih[h] + sjh[h] + se;
        v = v > 0.0f ? v : NEG_SLOPE * v;
        a[h] = v;
        atomicMax(&g_m[dst * 4 + h], f2key(v));
    }
    int pos = atomicAdd(&g_cur[dst], 1);
    g_ssrc[pos] = src;
    *((float4*)g_salpha + pos) = make_float4(a[0], a[1], a[2], a[3]);
}

// ---------------- K5: warp-per-node aggregation (fused softmax) -------------
__global__ __launch_bounds__(256) void k_aggr(const float* __restrict__ bias,
                                              float* __restrict__ out) {
    int w = (blockIdx.x * blockDim.x + threadIdx.x) >> 5;
    if (w >= N_NODES) return;
    int lane = threadIdx.x & 31;
    int h = lane >> 3;

    int start = g_off[w];
    int end   = g_off[w + 1];

    int mk = g_m[w * 4 + h];
    float m = 0.0f;
    if (mk != (int)0x80000000)
        m = __int_as_float(mk >= 0 ? mk : (mk ^ 0x7fffffff));

    float ax = 0.0f, ay = 0.0f, az = 0.0f, aw = 0.0f, den = 0.0f;

    #pragma unroll 2
    for (int e = start; e < end; e++) {
        int src = __ldg(&g_ssrc[e]);
        float a = __ldg(&g_salpha[(size_t)e * 4 + h]);
        float ea = __expf(a - m);
        den += ea;
        float4 xv = __ldg((const float4*)(g_xh + (size_t)src * 128) + lane);
        ax += ea * xv.x; ay += ea * xv.y; az += ea * xv.z; aw += ea * xv.w;
    }

    float inv = 1.0f / (den + 1e-16f);
    float4 b = __ldg((const float4*)bias + lane);
    ((float4*)out)[(size_t)w * 32 + lane] =
        make_float4(ax * inv + b.x, ay * inv + b.y, az * inv + b.z, aw * inv + b.w);
}

// ---------------- launch ----------------------------------------------------
extern "C" void kernel_launch(void* const* d_in, const int* in_sizes, int n_in,
                              void* d_out, int out_size) {
    const float* x     = (const float*)d_in[0];
    const int*   ei    = (const int*)  d_in[1];
    const float* eattr = (const float*)d_in[2];
    const float* W     = (const float*)d_in[3];
    const float* We    = (const float*)d_in[4];
    const float* att   = (const float*)d_in[5];
    const float* bias  = (const float*)d_in[6];
    float* out = (float*)d_out;

    k_init <<<(N_NODES * 4 + 255) / 256, 256>>>(We, att);
    k_hist <<<(N_EDGES + 255) / 256, 256>>>(ei);
    k_scan <<<1, 1024>>>();
    k_gemm <<<(N_NODES + 63) / 64, 256>>>(x, W, att);
    k_edge <<<(N_EDGES + 255) / 256, 256>>>(ei, eattr);
    k_aggr <<<((size_t)N_NODES * 32 + 255) / 256, 256>>>(bias, out);
}